// round 6
// baseline (speedup 1.0000x reference)
#include <cuda_runtime.h>

#define NB 8
#define NI 64
#define NO 64
#define NN 8192
#define NK 16
#define ND 3
#define NH1 16
#define NH2 32
#define TN 8                 // n values per CTA
#define ROWS 128             // TN * NK
#define NTHREADS 128
#define BON (NB*NO*NN)       // 4194304
#define SPN (NB*ND*NN)       // 196608

typedef unsigned long long u64;

// shared memory layout (floats):
//  sWp  : NI*NO   = 4096   (permuted weight)
//  sX   : NI*ROWS = 8192
//  sH2  : NH2*ROWS= 4096
//  sW3p : NH2*NO  = 2048   (permuted W3)
//  small: 48+16+512+32+64+64+512 = 1248
#define SMEM_FLOATS (4096+8192+4096+2048+1248)
#define SMEM_BYTES (SMEM_FLOATS*4)

__device__ __forceinline__ u64 pack2(float x, float y) {
    u64 r; asm("mov.b64 %0,{%1,%2};" : "=l"(r) : "f"(x), "f"(y)); return r;
}
__device__ __forceinline__ u64 fma2(u64 a, u64 b, u64 c) {
    u64 d; asm("fma.rn.f32x2 %0,%1,%2,%3;" : "=l"(d) : "l"(a), "l"(b), "l"(c)); return d;
}
__device__ __forceinline__ float2 unpack2(u64 v) {
    float2 f; asm("mov.b64 {%0,%1},%2;" : "=f"(f.x), "=f"(f.y) : "l"(v)); return f;
}

// permuted index within a 64-float weight row: all tc half0 chunks, then half1.
__device__ __forceinline__ int wperm(int o) {
    return ((o >> 2) & 1) * 32 + (o >> 3) * 4 + (o & 3);
}

__global__ void __launch_bounds__(NTHREADS, 2)
pccn_kernel(const float* __restrict__ input, const float* __restrict__ points,
            const float* __restrict__ support, const float* __restrict__ weight,
            const float* __restrict__ bias, const float* __restrict__ W1,
            const float* __restrict__ b1, const float* __restrict__ W2,
            const float* __restrict__ b2, const float* __restrict__ W3,
            const float* __restrict__ b3, float* __restrict__ out, int copy_sp)
{
    extern __shared__ float sm[];
    float* sWp   = sm;                    // [i][perm(o)]
    float* sX    = sWp + 4096;            // [i][row]
    float* sH2   = sX  + 8192;            // [j][row]
    float* sW3p  = sH2 + 4096;            // [j][perm(o)]
    float* sW1   = sW3p + 2048;           // 3x16
    float* sb1   = sW1 + 48;
    float* sW2   = sb1 + 16;              // 16x32
    float* sb2   = sW2 + 512;
    float* sb3   = sb2 + 32;
    float* sBias = sb3 + 64;
    float* sOut  = sBias + 64;            // [n_local][o] 8x64

    const int tid = threadIdx.x;
    const int blk = blockIdx.x;
    const int b   = blk >> 10;            // NN/TN = 1024 tiles per batch
    const int n0  = (blk & 1023) * TN;

    // ---- cooperative loads to smem ----
    for (int idx = tid; idx < NI*NO; idx += NTHREADS) {
        int i = idx >> 6, o = idx & 63;
        sWp[i*NO + wperm(o)] = weight[idx];
    }
    for (int idx = tid; idx < NH2*NO; idx += NTHREADS) {
        int j = idx >> 6, o = idx & 63;
        sW3p[j*NO + wperm(o)] = W3[idx];
    }
    for (int idx = tid; idx < (NI*ROWS)/4; idx += NTHREADS) {
        int i = idx >> 5, c = idx & 31;   // 32 float4 per i-row
        ((float4*)(sX + i*ROWS))[c] =
            *(const float4*)(input + (((size_t)b*NI + i)*NN + n0)*NK + c*4);
    }
    for (int idx = tid; idx < NH1*NH2; idx += NTHREADS) sW2[idx] = W2[idx];
    if (tid < 48) sW1[tid]  = W1[tid];
    if (tid < 16) sb1[tid]  = b1[tid];
    if (tid < 32) sb2[tid]  = b2[tid];
    if (tid < 64) sb3[tid]  = b3[tid];
    if (tid < 64) sBias[tid] = bias[tid];

    // ---- per-row (b,n,k) relative coords + normalization (one row/thread) ----
    float x0, x1, x2;
    {
        const int k = tid & 15;
        const int n = n0 + (tid >> 4);
        float p0 = points[(((size_t)b*ND + 0)*NN + n)*NK + k] - support[((size_t)b*ND + 0)*NN + n];
        float p1 = points[(((size_t)b*ND + 1)*NN + n)*NK + k] - support[((size_t)b*ND + 1)*NN + n];
        float p2 = points[(((size_t)b*ND + 2)*NN + n)*NK + k] - support[((size_t)b*ND + 2)*NN + n];
        float sq = p0*p0 + p1*p1 + p2*p2;
        float m = sq;
#pragma unroll
        for (int off = 8; off > 0; off >>= 1)
            m = fmaxf(m, __shfl_xor_sync(0xffffffffu, m, off));
        float maxi = sqrtf(m);
        maxi += (maxi == 0.0f) ? 1.0f : 0.0f;
        float inv = 1.0f / maxi;
        x0 = p0*inv; x1 = p1*inv; x2 = p2*inv;
    }

    __syncthreads();   // weights ready

    // ---- tiny MLP to h2 (one row per thread) ----
    {
        float h1[NH1];
#pragma unroll
        for (int a = 0; a < NH1; a++) {
            float v = sb1[a] + x0*sW1[a] + x1*sW1[16 + a] + x2*sW1[32 + a];
            h1[a] = fmaxf(v, 0.0f);
        }
        u64 h2p[NH2/2];
#pragma unroll
        for (int jp = 0; jp < NH2/2; jp++) h2p[jp] = ((const u64*)sb2)[jp];
#pragma unroll
        for (int a = 0; a < NH1; a++) {
            u64 xd = pack2(h1[a], h1[a]);
            const u64* wrow = (const u64*)(sW2 + a*NH2);
#pragma unroll
            for (int jp = 0; jp < NH2/2; jp++) h2p[jp] = fma2(xd, wrow[jp], h2p[jp]);
        }
#pragma unroll
        for (int jp = 0; jp < NH2/2; jp++) {
            float2 v = unpack2(h2p[jp]);
            sH2[(2*jp+0)*ROWS + tid] = fmaxf(v.x, 0.0f);
            sH2[(2*jp+1)*ROWS + tid] = fmaxf(v.y, 0.0f);
        }
    }

    __syncthreads();

    // ---- two register-tiled GEMMs, per-thread tile 8 rows x 8 o ----
    // f32x2 acc packed along o: acc[rr][op] = (o0+2op, o0+2op+1)
    const int tr = tid >> 3, tc = tid & 7;
    const int row0 = tr * 8, o0 = tc * 8;
    const int wofs = tc * 4;                 // float offset of half0 chunk

    // mat = h2 @ W3 + b3   (K-dim 32), software-pipelined
    u64 macc[8][4];
    {
        const u64* bp = (const u64*)(sb3 + o0);
        u64 b0 = bp[0], b1v = bp[1], b2v = bp[2], b3v = bp[3];
#pragma unroll
        for (int rr = 0; rr < 8; rr++) {
            macc[rr][0] = b0; macc[rr][1] = b1v; macc[rr][2] = b2v; macc[rr][3] = b3v;
        }
    }
    {
        float4 xa = *(const float4*)(sH2 + row0);
        float4 xb = *(const float4*)(sH2 + row0 + 4);
        ulonglong2 wlo = *(const ulonglong2*)(sW3p + wofs);
        ulonglong2 whi = *(const ulonglong2*)(sW3p + wofs + 32);
#pragma unroll 8
        for (int j = 0; j < NH2; j++) {
            // prefetch j+1 (stays inside smem; last prefetch unused)
            const float* xsrc = sH2 + (j+1)*ROWS + row0;
            const float* wsrc = sW3p + (j+1)*NO + wofs;
            float4 xan = *(const float4*)(xsrc);
            float4 xbn = *(const float4*)(xsrc + 4);
            ulonglong2 wlon = *(const ulonglong2*)(wsrc);
            ulonglong2 whin = *(const ulonglong2*)(wsrc + 32);

            u64 xd[8];
            xd[0]=pack2(xa.x,xa.x); xd[1]=pack2(xa.y,xa.y);
            xd[2]=pack2(xa.z,xa.z); xd[3]=pack2(xa.w,xa.w);
            xd[4]=pack2(xb.x,xb.x); xd[5]=pack2(xb.y,xb.y);
            xd[6]=pack2(xb.z,xb.z); xd[7]=pack2(xb.w,xb.w);
            u64 w[4] = {wlo.x, wlo.y, whi.x, whi.y};
#pragma unroll
            for (int rr = 0; rr < 8; rr++)
#pragma unroll
                for (int op = 0; op < 4; op++)
                    macc[rr][op] = fma2(xd[rr], w[op], macc[rr][op]);

            xa = xan; xb = xbn; wlo = wlon; whi = whin;
        }
    }

    // F = X^T @ weight   (K-dim 64), software-pipelined
    u64 facc[8][4];
#pragma unroll
    for (int rr = 0; rr < 8; rr++)
#pragma unroll
        for (int op = 0; op < 4; op++) facc[rr][op] = 0ull;

    {
        float4 xa = *(const float4*)(sX + row0);
        float4 xb = *(const float4*)(sX + row0 + 4);
        ulonglong2 wlo = *(const ulonglong2*)(sWp + wofs);
        ulonglong2 whi = *(const ulonglong2*)(sWp + wofs + 32);
#pragma unroll 8
        for (int i = 0; i < NI; i++) {
            const float* xsrc = sX + (i+1)*ROWS + row0;
            const float* wsrc = sWp + (i+1)*NO + wofs;
            float4 xan = *(const float4*)(xsrc);
            float4 xbn = *(const float4*)(xsrc + 4);
            ulonglong2 wlon = *(const ulonglong2*)(wsrc);
            ulonglong2 whin = *(const ulonglong2*)(wsrc + 32);

            u64 xd[8];
            xd[0]=pack2(xa.x,xa.x); xd[1]=pack2(xa.y,xa.y);
            xd[2]=pack2(xa.z,xa.z); xd[3]=pack2(xa.w,xa.w);
            xd[4]=pack2(xb.x,xb.x); xd[5]=pack2(xb.y,xb.y);
            xd[6]=pack2(xb.z,xb.z); xd[7]=pack2(xb.w,xb.w);
            u64 w[4] = {wlo.x, wlo.y, whi.x, whi.y};
#pragma unroll
            for (int rr = 0; rr < 8; rr++)
#pragma unroll
                for (int op = 0; op < 4; op++)
                    facc[rr][op] = fma2(xd[rr], w[op], facc[rr][op]);

            xa = xan; xb = xbn; wlo = wlon; whi = whin;
        }
    }

    // ---- combine: elementwise product, reduce over 8 rows in-thread ----
    float v[8];
#pragma unroll
    for (int op = 0; op < 4; op++) {
        u64 p = fma2(facc[0][op], macc[0][op], 0ull);
#pragma unroll
        for (int rr = 1; rr < 8; rr++)
            p = fma2(facc[rr][op], macc[rr][op], p);
        float2 f = unpack2(p);
        v[2*op]   = f.x;
        v[2*op+1] = f.y;
    }
    // rows row0..row0+7 all in n_local = tr>>1; partner thread is tid^8
#pragma unroll
    for (int oo = 0; oo < 8; oo++)
        v[oo] += __shfl_xor_sync(0xffffffffu, v[oo], 8);

    const int lid = tid & 31;
    const int n_local = tid >> 4;
    if (((lid >> 3) & 1) == 0) {   // lanes 0-7 and 16-23 write
        float4 a = make_float4(v[0], v[1], v[2], v[3]);
        float4 c = make_float4(v[4], v[5], v[6], v[7]);
        *(float4*)(sOut + n_local*NO + (lid&7)*8)     = a;
        *(float4*)(sOut + n_local*NO + (lid&7)*8 + 4) = c;
    }

    __syncthreads();

    // ---- epilogue: out layout (B, O, N), + bias ----
    {
        int o = tid >> 1, half = tid & 1;
        float4 r;
        r.x = sOut[(half*4+0)*NO + o] + sBias[o];
        r.y = sOut[(half*4+1)*NO + o] + sBias[o];
        r.z = sOut[(half*4+2)*NO + o] + sBias[o];
        r.w = sOut[(half*4+3)*NO + o] + sBias[o];
        *(float4*)(out + ((size_t)b*NO + o)*NN + n0 + half*4) = r;
    }

    // ---- second tuple element: support_points passthrough ----
    if (copy_sp) {
        for (int idx = blk*NTHREADS + tid; idx < SPN; idx += gridDim.x*NTHREADS)
            out[BON + idx] = support[idx];
    }
}

extern "C" void kernel_launch(void* const* d_in, const int* in_sizes, int n_in,
                              void* d_out, int out_size) {
    const float* input   = (const float*)d_in[0];
    const float* points  = (const float*)d_in[1];
    const float* support = (const float*)d_in[2];
    const float* weight  = (const float*)d_in[3];
    const float* bias    = (const float*)d_in[4];
    const float* W1      = (const float*)d_in[5];
    const float* b1      = (const float*)d_in[6];
    const float* W2      = (const float*)d_in[7];
    const float* b2      = (const float*)d_in[8];
    const float* W3      = (const float*)d_in[9];
    const float* b3      = (const float*)d_in[10];

    static int inited = 0;
    if (!inited) {
        cudaFuncSetAttribute(pccn_kernel,
                             cudaFuncAttributeMaxDynamicSharedMemorySize,
                             SMEM_BYTES);
        inited = 1;
    }
    int copy_sp = (out_size > BON) ? 1 : 0;
    pccn_kernel<<<NB*(NN/TN), NTHREADS, SMEM_BYTES>>>(
        input, points, support, weight, bias, W1, b1, W2, b2, W3, b3,
        (float*)d_out, copy_sp);
}

// round 7
// speedup vs baseline: 1.0985x; 1.0985x over previous
#include <cuda_runtime.h>

#define NB 8
#define NI 64
#define NO 64
#define NN 8192
#define NK 16
#define ND 3
#define NH1 16
#define NH2 32
#define TN 8                 // n values per CTA
#define ROWS 128             // TN * NK
#define NTHREADS 256
#define BON (NB*NO*NN)       // 4194304
#define SPN (NB*ND*NN)       // 196608

typedef unsigned long long u64;

// shared memory layout (floats):
//  sWp  : NI*NO   = 4096   (permuted weight)
//  sX   : NI*ROWS = 8192
//  sH2  : NH2*ROWS= 4096
//  sW3p : NH2*NO  = 2048   (permuted W3)
//  small: 48+16+512+32+64+64+512 = 1248
#define SMEM_FLOATS (4096+8192+4096+2048+1248)
#define SMEM_BYTES (SMEM_FLOATS*4)

__device__ __forceinline__ u64 pack2(float x, float y) {
    u64 r; asm("mov.b64 %0,{%1,%2};" : "=l"(r) : "f"(x), "f"(y)); return r;
}
__device__ __forceinline__ u64 fma2(u64 a, u64 b, u64 c) {
    u64 d; asm("fma.rn.f32x2 %0,%1,%2,%3;" : "=l"(d) : "l"(a), "l"(b), "l"(c)); return d;
}
__device__ __forceinline__ float2 unpack2(u64 v) {
    float2 f; asm("mov.b64 {%0,%1},%2;" : "=f"(f.x), "=f"(f.y) : "l"(v)); return f;
}

// permuted index within a 64-float weight row: all tc half0 chunks, then half1.
__device__ __forceinline__ int wperm(int o) {
    return ((o >> 2) & 1) * 32 + (o >> 3) * 4 + (o & 3);
}

__global__ void __launch_bounds__(NTHREADS, 2)
pccn_kernel(const float* __restrict__ input, const float* __restrict__ points,
            const float* __restrict__ support, const float* __restrict__ weight,
            const float* __restrict__ bias, const float* __restrict__ W1,
            const float* __restrict__ b1, const float* __restrict__ W2,
            const float* __restrict__ b2, const float* __restrict__ W3,
            const float* __restrict__ b3, float* __restrict__ out, int copy_sp)
{
    extern __shared__ float sm[];
    float* sWp   = sm;                    // [i][perm(o)]
    float* sX    = sWp + 4096;            // [i][row]
    float* sH2   = sX  + 8192;            // [j][row]
    float* sW3p  = sH2 + 4096;            // [j][perm(o)]
    float* sW1   = sW3p + 2048;           // 3x16
    float* sb1   = sW1 + 48;
    float* sW2   = sb1 + 16;              // 16x32
    float* sb2   = sW2 + 512;
    float* sb3   = sb2 + 32;
    float* sBias = sb3 + 64;
    float* sOut  = sBias + 64;            // [n_local][o] 8x64

    const int tid = threadIdx.x;
    const int blk = blockIdx.x;
    const int b   = blk >> 10;            // NN/TN = 1024 tiles per batch
    const int n0  = (blk & 1023) * TN;

    // ---- cooperative loads to smem ----
    for (int idx = tid; idx < NI*NO; idx += NTHREADS) {
        int i = idx >> 6, o = idx & 63;
        sWp[i*NO + wperm(o)] = weight[idx];
    }
    for (int idx = tid; idx < NH2*NO; idx += NTHREADS) {
        int j = idx >> 6, o = idx & 63;
        sW3p[j*NO + wperm(o)] = W3[idx];
    }
    for (int idx = tid; idx < (NI*ROWS)/4; idx += NTHREADS) {
        int i = idx >> 5, c = idx & 31;   // 32 float4 per i-row
        ((float4*)(sX + i*ROWS))[c] =
            *(const float4*)(input + (((size_t)b*NI + i)*NN + n0)*NK + c*4);
    }
    for (int idx = tid; idx < NH1*NH2; idx += NTHREADS) sW2[idx] = W2[idx];
    if (tid < 48) sW1[tid]  = W1[tid];
    if (tid < 16) sb1[tid]  = b1[tid];
    if (tid < 32) sb2[tid]  = b2[tid];
    if (tid < 64) sb3[tid]  = b3[tid];
    if (tid < 64) sBias[tid] = bias[tid];

    // ---- per-row (b,n,k) relative coords + normalization (threads 0..127) ----
    float x0 = 0.f, x1 = 0.f, x2 = 0.f;
    if (tid < ROWS) {
        const int k = tid & 15;
        const int n = n0 + (tid >> 4);
        float p0 = points[(((size_t)b*ND + 0)*NN + n)*NK + k] - support[((size_t)b*ND + 0)*NN + n];
        float p1 = points[(((size_t)b*ND + 1)*NN + n)*NK + k] - support[((size_t)b*ND + 1)*NN + n];
        float p2 = points[(((size_t)b*ND + 2)*NN + n)*NK + k] - support[((size_t)b*ND + 2)*NN + n];
        float sq = p0*p0 + p1*p1 + p2*p2;
        float m = sq;
#pragma unroll
        for (int off = 8; off > 0; off >>= 1)
            m = fmaxf(m, __shfl_xor_sync(0xffffffffu, m, off));
        float maxi = sqrtf(m);
        maxi += (maxi == 0.0f) ? 1.0f : 0.0f;
        float inv = 1.0f / maxi;
        x0 = p0*inv; x1 = p1*inv; x2 = p2*inv;
    }

    __syncthreads();   // weights ready

    // ---- tiny MLP to h2 (threads 0..127, one row each) ----
    if (tid < ROWS) {
        float h1[NH1];
#pragma unroll
        for (int a = 0; a < NH1; a++) {
            float v = sb1[a] + x0*sW1[a] + x1*sW1[16 + a] + x2*sW1[32 + a];
            h1[a] = fmaxf(v, 0.0f);
        }
        u64 h2p[NH2/2];
#pragma unroll
        for (int jp = 0; jp < NH2/2; jp++) h2p[jp] = ((const u64*)sb2)[jp];
#pragma unroll
        for (int a = 0; a < NH1; a++) {
            u64 xd = pack2(h1[a], h1[a]);
            const u64* wrow = (const u64*)(sW2 + a*NH2);
#pragma unroll
            for (int jp = 0; jp < NH2/2; jp++) h2p[jp] = fma2(xd, wrow[jp], h2p[jp]);
        }
#pragma unroll
        for (int jp = 0; jp < NH2/2; jp++) {
            float2 v = unpack2(h2p[jp]);
            sH2[(2*jp+0)*ROWS + tid] = fmaxf(v.x, 0.0f);
            sH2[(2*jp+1)*ROWS + tid] = fmaxf(v.y, 0.0f);
        }
    }

    __syncthreads();

    // ---- two register-tiled GEMMs, per-thread tile 4 rows x 8 o ----
    // f32x2 acc packed along o: acc[rr][op] = (o0+2op, o0+2op+1)
    const int tr = tid >> 3, tc = tid & 7;
    const int row0 = tr * 4, o0 = tc * 8;
    const int wofs = tc * 4;                 // float offset of half0 chunk

    // mat = h2 @ W3 + b3   (K-dim 32), prefetch-1 pipelined
    u64 macc[4][4];
    {
#pragma unroll
        for (int op = 0; op < 4; op++) {
            u64 bp = pack2(sb3[o0 + 2*op], sb3[o0 + 2*op + 1]);
            macc[0][op] = bp; macc[1][op] = bp; macc[2][op] = bp; macc[3][op] = bp;
        }
    }
    {
        float4 xa = *(const float4*)(sH2 + row0);
        ulonglong2 wlo = *(const ulonglong2*)(sW3p + wofs);
        ulonglong2 whi = *(const ulonglong2*)(sW3p + wofs + 32);
#pragma unroll 8
        for (int j = 0; j < NH2; j++) {
            // prefetch j+1 (last one reads into sW3p/sW1 region — harmless)
            float4 xan = *(const float4*)(sH2 + (j+1)*ROWS + row0);
            ulonglong2 wlon = *(const ulonglong2*)(sW3p + (j+1)*NO + wofs);
            ulonglong2 whin = *(const ulonglong2*)(sW3p + (j+1)*NO + wofs + 32);

            u64 w[4] = {wlo.x, wlo.y, whi.x, whi.y};
            {
                u64 xd = pack2(xa.x, xa.x);
#pragma unroll
                for (int op = 0; op < 4; op++) macc[0][op] = fma2(xd, w[op], macc[0][op]);
            }
            {
                u64 xd = pack2(xa.y, xa.y);
#pragma unroll
                for (int op = 0; op < 4; op++) macc[1][op] = fma2(xd, w[op], macc[1][op]);
            }
            {
                u64 xd = pack2(xa.z, xa.z);
#pragma unroll
                for (int op = 0; op < 4; op++) macc[2][op] = fma2(xd, w[op], macc[2][op]);
            }
            {
                u64 xd = pack2(xa.w, xa.w);
#pragma unroll
                for (int op = 0; op < 4; op++) macc[3][op] = fma2(xd, w[op], macc[3][op]);
            }
            xa = xan; wlo = wlon; whi = whin;
        }
    }

    // F = X^T @ weight   (K-dim 64), prefetch-1 pipelined
    u64 facc[4][4];
#pragma unroll
    for (int rr = 0; rr < 4; rr++)
#pragma unroll
        for (int op = 0; op < 4; op++) facc[rr][op] = 0ull;

    {
        float4 xa = *(const float4*)(sX + row0);
        ulonglong2 wlo = *(const ulonglong2*)(sWp + wofs);
        ulonglong2 whi = *(const ulonglong2*)(sWp + wofs + 32);
#pragma unroll 8
        for (int i = 0; i < NI; i++) {
            // prefetch i+1 (i==63 reads into sX start — harmless)
            float4 xan = *(const float4*)(sX + (i+1)*ROWS + row0);
            ulonglong2 wlon = *(const ulonglong2*)(sWp + (i+1)*NO + wofs);
            ulonglong2 whin = *(const ulonglong2*)(sWp + (i+1)*NO + wofs + 32);

            u64 w[4] = {wlo.x, wlo.y, whi.x, whi.y};
            {
                u64 xd = pack2(xa.x, xa.x);
#pragma unroll
                for (int op = 0; op < 4; op++) facc[0][op] = fma2(xd, w[op], facc[0][op]);
            }
            {
                u64 xd = pack2(xa.y, xa.y);
#pragma unroll
                for (int op = 0; op < 4; op++) facc[1][op] = fma2(xd, w[op], facc[1][op]);
            }
            {
                u64 xd = pack2(xa.z, xa.z);
#pragma unroll
                for (int op = 0; op < 4; op++) facc[2][op] = fma2(xd, w[op], facc[2][op]);
            }
            {
                u64 xd = pack2(xa.w, xa.w);
#pragma unroll
                for (int op = 0; op < 4; op++) facc[3][op] = fma2(xd, w[op], facc[3][op]);
            }
            xa = xan; wlo = wlon; whi = whin;
        }
    }

    // ---- combine: elementwise product, reduce over 4 rows in-thread ----
    float v[8];
#pragma unroll
    for (int op = 0; op < 4; op++) {
        u64 p = fma2(facc[0][op], macc[0][op], 0ull);
        p = fma2(facc[1][op], macc[1][op], p);
        p = fma2(facc[2][op], macc[2][op], p);
        p = fma2(facc[3][op], macc[3][op], p);
        float2 f = unpack2(p);
        v[2*op]   = f.x;
        v[2*op+1] = f.y;
    }
    // reduce across the 4 lanes (xor 8, 16) that share (n_local, o0)
#pragma unroll
    for (int oo = 0; oo < 8; oo++) {
        v[oo] += __shfl_xor_sync(0xffffffffu, v[oo], 8);
        v[oo] += __shfl_xor_sync(0xffffffffu, v[oo], 16);
    }
    // warp w owns n_local = w; lanes 0..7 write 8 o each
    const int lid = tid & 31;
    const int n_local = tid >> 5;
    if (lid < 8) {
        float4 a = make_float4(v[0], v[1], v[2], v[3]);
        float4 c = make_float4(v[4], v[5], v[6], v[7]);
        *(float4*)(sOut + n_local*NO + lid*8)     = a;
        *(float4*)(sOut + n_local*NO + lid*8 + 4) = c;
    }

    __syncthreads();

    // ---- epilogue: out layout (B, O, N), + bias ----
    if (tid < 128) {
        int o = tid >> 1, half = tid & 1;
        float4 r;
        r.x = sOut[(half*4+0)*NO + o] + sBias[o];
        r.y = sOut[(half*4+1)*NO + o] + sBias[o];
        r.z = sOut[(half*4+2)*NO + o] + sBias[o];
        r.w = sOut[(half*4+3)*NO + o] + sBias[o];
        *(float4*)(out + ((size_t)b*NO + o)*NN + n0 + half*4) = r;
    }

    // ---- second tuple element: support_points passthrough ----
    if (copy_sp) {
        for (int idx = blk*NTHREADS + tid; idx < SPN; idx += gridDim.x*NTHREADS)
            out[BON + idx] = support[idx];
    }
}

extern "C" void kernel_launch(void* const* d_in, const int* in_sizes, int n_in,
                              void* d_out, int out_size) {
    const float* input   = (const float*)d_in[0];
    const float* points  = (const float*)d_in[1];
    const float* support = (const float*)d_in[2];
    const float* weight  = (const float*)d_in[3];
    const float* bias    = (const float*)d_in[4];
    const float* W1      = (const float*)d_in[5];
    const float* b1      = (const float*)d_in[6];
    const float* W2      = (const float*)d_in[7];
    const float* b2      = (const float*)d_in[8];
    const float* W3      = (const float*)d_in[9];
    const float* b3      = (const float*)d_in[10];

    static int inited = 0;
    if (!inited) {
        cudaFuncSetAttribute(pccn_kernel,
                             cudaFuncAttributeMaxDynamicSharedMemorySize,
                             SMEM_BYTES);
        inited = 1;
    }
    int copy_sp = (out_size > BON) ? 1 : 0;
    pccn_kernel<<<NB*(NN/TN), NTHREADS, SMEM_BYTES>>>(
        input, points, support, weight, bias, W1, b1, W2, b2, W3, b3,
        (float*)d_out, copy_sp);
}

// round 9
// speedup vs baseline: 1.7549x; 1.5975x over previous
#include <cuda_runtime.h>
#include <cuda_bf16.h>

#define NB 8
#define NI 64
#define NO 64
#define NN 8192
#define NK 16
#define ND 3
#define NH1 16
#define NH2 32
#define TN 8
#define ROWS 128
#define NTHREADS 256
#define BON (NB*NO*NN)
#define SPN (NB*ND*NN)

typedef unsigned long long u64;
typedef unsigned int u32;

// ---- smem byte offsets: pre-fragmented operands for mma.sync m16n8k16 ----
// A-frag GEMM1 (X):  [w:8][s:4][lane:32] x uint4   = 16384 B per half
// B-frag GEMM1 (W):  [nt:8][s:4][lane:32] x uint2  =  8192 B per half
// A-frag GEMM2 (H):  [w:8][s:2][lane:32] x uint4   =  8192 B per half
// B-frag GEMM2 (W3): [nt:8][s:2][lane:32] x uint2  =  4096 B per half
#define SM_AFH  0
#define SM_AFL  16384
#define SM_BFH  32768
#define SM_BFL  40960
#define SM_HFH  49152
#define SM_HFL  57344
#define SM_B2FH 65536
#define SM_B2FL 69632
#define SM_SMALL 73728
#define SMEM_BYTES (SM_SMALL + 1248*4)

__device__ __forceinline__ u64 pack2(float x, float y) {
    u64 r; asm("mov.b64 %0,{%1,%2};" : "=l"(r) : "f"(x), "f"(y)); return r;
}
__device__ __forceinline__ u64 fma2(u64 a, u64 b, u64 c) {
    u64 d; asm("fma.rn.f32x2 %0,%1,%2,%3;" : "=l"(d) : "l"(a), "l"(b), "l"(c)); return d;
}
__device__ __forceinline__ float2 unpack2(u64 v) {
    float2 f; asm("mov.b64 {%0,%1},%2;" : "=f"(f.x), "=f"(f.y) : "l"(v)); return f;
}
__device__ __forceinline__ u32 bf2bits(__nv_bfloat162 h) { return *reinterpret_cast<u32*>(&h); }

// split a float pair into bf16 hi / lo words (low half = first element)
__device__ __forceinline__ void split_pair(float f0, float f1, u32& hi, u32& lo) {
    __nv_bfloat162 hb = __float22bfloat162_rn(make_float2(f0, f1));
    float2 hf = __bfloat1622float2(hb);
    __nv_bfloat162 lb = __float22bfloat162_rn(make_float2(f0 - hf.x, f1 - hf.y));
    hi = bf2bits(hb); lo = bf2bits(lb);
}

#define MMA16816(c, a, b) \
    asm volatile("mma.sync.aligned.m16n8k16.row.col.f32.bf16.bf16.f32 " \
        "{%0,%1,%2,%3}, {%4,%5,%6,%7}, {%8,%9}, {%0,%1,%2,%3};" \
        : "+f"((c)[0]), "+f"((c)[1]), "+f"((c)[2]), "+f"((c)[3]) \
        : "r"((a).x), "r"((a).y), "r"((a).z), "r"((a).w), \
          "r"((b).x), "r"((b).y))

__global__ void __launch_bounds__(NTHREADS, 2)
pccn_kernel(const float* __restrict__ input, const float* __restrict__ points,
            const float* __restrict__ support, const float* __restrict__ weight,
            const float* __restrict__ bias, const float* __restrict__ W1,
            const float* __restrict__ b1, const float* __restrict__ W2,
            const float* __restrict__ b2, const float* __restrict__ W3,
            const float* __restrict__ b3, float* __restrict__ out, int copy_sp)
{
    extern __shared__ char smemc[];
    u32* aFH  = (u32*)(smemc + SM_AFH);
    u32* aFL  = (u32*)(smemc + SM_AFL);
    u32* bFH  = (u32*)(smemc + SM_BFH);
    u32* bFL  = (u32*)(smemc + SM_BFL);
    u32* hFH  = (u32*)(smemc + SM_HFH);
    u32* hFL  = (u32*)(smemc + SM_HFL);
    u32* b2FH = (u32*)(smemc + SM_B2FH);
    u32* b2FL = (u32*)(smemc + SM_B2FL);
    float* sW1   = (float*)(smemc + SM_SMALL);
    float* sb1   = sW1 + 48;
    float* sW2   = sb1 + 16;
    float* sb2   = sW2 + 512;
    float* sb3   = sb2 + 32;
    float* sBias = sb3 + 64;
    float* sOut  = sBias + 64;        // [n_local:8][o:64]

    const int tid  = threadIdx.x;
    const int warp = tid >> 5;
    const int lane = tid & 31;
    const int blk  = blockIdx.x;
    const int b    = blk >> 10;
    const int n0   = (blk & 1023) * TN;

    // ================= staging: X -> A-frags (GEMM1) =================
    // A[row][c] = input[b][c][n0 + row/16][row%16], row = n_loc*16 + k
#pragma unroll
    for (int it = 0; it < 16; it++) {
        int idx = tid + it*NTHREADS;         // 0..4095 over (cp:32, row:128)
        int row = idx & 127;
        int cp  = idx >> 7;                  // c = 2*cp
        const float* base = input + (((size_t)b*NI + 2*cp)*NN + n0)*NK;
        float f0 = base[row];
        float f1 = base[(size_t)NN*NK + row];
        u32 hi, lo; split_pair(f0, f1, hi, lo);
        int w = row >> 4, gid = row & 7, rb0 = (row >> 3) & 1;
        int c = 2*cp;
        int s = c >> 4, tig = (c >> 1) & 3, rb1 = (c >> 3) & 1;
        int word = (((w*4 + s)*32) + gid*4 + tig)*4 + (rb1*2 + rb0);
        aFH[word] = hi; aFL[word] = lo;
    }
    // ================= staging: W -> B-frags (GEMM1) =================
    // b-word(nt,s,lane,rb) = {W[k][n], W[k+1][n]}, k = 16s+2tig+8rb, n = 8nt+gid
#pragma unroll
    for (int it = 0; it < 8; it++) {
        int idx = tid + it*NTHREADS;         // 0..2047 over (kh:32, n:64)
        int n  = idx & 63;
        int kh = idx >> 6;                   // k = 2*kh
        float f0 = weight[(2*kh)*NO + n];
        float f1 = weight[(2*kh + 1)*NO + n];
        u32 hi, lo; split_pair(f0, f1, hi, lo);
        int s = kh >> 3, tig = kh & 3, rb = (kh >> 2) & 1;
        int gid = n & 7, nt = n >> 3;
        int word = (((nt*4 + s)*32) + gid*4 + tig)*2 + rb;
        bFH[word] = hi; bFL[word] = lo;
    }
    // ================= staging: W3 -> B-frags (GEMM2) =================
#pragma unroll
    for (int it = 0; it < 4; it++) {
        int idx = tid + it*NTHREADS;         // 0..1023 over (kh:16, n:64)
        int n  = idx & 63;
        int kh = idx >> 6;
        float f0 = W3[(2*kh)*NO + n];
        float f1 = W3[(2*kh + 1)*NO + n];
        u32 hi, lo; split_pair(f0, f1, hi, lo);
        int s = kh >> 3, tig = kh & 3, rb = (kh >> 2) & 1;
        int gid = n & 7, nt = n >> 3;
        int word = (((nt*2 + s)*32) + gid*4 + tig)*2 + rb;
        b2FH[word] = hi; b2FL[word] = lo;
    }
    // ---- small arrays ----
    for (int idx = tid; idx < NH1*NH2; idx += NTHREADS) sW2[idx] = W2[idx];
    if (tid < 48) sW1[tid]  = W1[tid];
    if (tid < 16) sb1[tid]  = b1[tid];
    if (tid < 32) sb2[tid]  = b2[tid];
    if (tid < 64) sb3[tid]  = b3[tid];
    if (tid < 64) sBias[tid] = bias[tid];

    __syncthreads();

    // ============ coords + MLP -> H-frags (threads 0..127, row = tid) ============
    if (tid < ROWS) {
        const int row = tid;
        const int k = row & 15;
        const int n = n0 + (row >> 4);
        float p0 = points[(((size_t)b*ND + 0)*NN + n)*NK + k] - support[((size_t)b*ND + 0)*NN + n];
        float p1 = points[(((size_t)b*ND + 1)*NN + n)*NK + k] - support[((size_t)b*ND + 1)*NN + n];
        float p2 = points[(((size_t)b*ND + 2)*NN + n)*NK + k] - support[((size_t)b*ND + 2)*NN + n];
        float sq = p0*p0 + p1*p1 + p2*p2;
        float m = sq;
#pragma unroll
        for (int off = 8; off > 0; off >>= 1)
            m = fmaxf(m, __shfl_xor_sync(0xffffffffu, m, off));
        float maxi = sqrtf(m);
        maxi += (maxi == 0.0f) ? 1.0f : 0.0f;
        float inv = 1.0f / maxi;
        float x0 = p0*inv, x1 = p1*inv, x2 = p2*inv;

        float h1[NH1];
#pragma unroll
        for (int a = 0; a < NH1; a++) {
            float v = sb1[a] + x0*sW1[a] + x1*sW1[16 + a] + x2*sW1[32 + a];
            h1[a] = fmaxf(v, 0.0f);
        }
        u64 h2p[NH2/2];
#pragma unroll
        for (int jp = 0; jp < NH2/2; jp++) h2p[jp] = ((const u64*)sb2)[jp];
#pragma unroll
        for (int a = 0; a < NH1; a++) {
            u64 xd = pack2(h1[a], h1[a]);
            const u64* wrow = (const u64*)(sW2 + a*NH2);
#pragma unroll
            for (int jp = 0; jp < NH2/2; jp++) h2p[jp] = fma2(xd, wrow[jp], h2p[jp]);
        }
        const int w = row >> 4, gid = row & 7, rb0 = (row >> 3) & 1;
#pragma unroll
        for (int jp = 0; jp < 16; jp++) {
            float2 v = unpack2(h2p[jp]);
            v.x = fmaxf(v.x, 0.0f); v.y = fmaxf(v.y, 0.0f);
            u32 hi, lo; split_pair(v.x, v.y, hi, lo);
            int s = jp >> 3, tig = jp & 3, rb1 = (jp >> 2) & 1;
            int word = (((w*2 + s)*32) + gid*4 + tig)*4 + (rb1*2 + rb0);
            hFH[word] = hi; hFL[word] = lo;
        }
    }

    __syncthreads();

    // ================= GEMMs via mma.sync (warp w -> rows 16w..16w+15 = n_local w) =================
    float c1[8][4], c2[8][4];
#pragma unroll
    for (int nt = 0; nt < 8; nt++)
#pragma unroll
        for (int r = 0; r < 4; r++) { c1[nt][r] = 0.0f; c2[nt][r] = 0.0f; }

    // GEMM1: C1 = X @ W (K=64)
#pragma unroll
    for (int s = 0; s < 4; s++) {
        uint4 ah = ((const uint4*)aFH)[(warp*4 + s)*32 + lane];
        uint4 al = ((const uint4*)aFL)[(warp*4 + s)*32 + lane];
#pragma unroll
        for (int nt = 0; nt < 8; nt++) {
            uint2 bh = ((const uint2*)bFH)[(nt*4 + s)*32 + lane];
            uint2 bl = ((const uint2*)bFL)[(nt*4 + s)*32 + lane];
            MMA16816(c1[nt], ah, bh);
            MMA16816(c1[nt], ah, bl);
            MMA16816(c1[nt], al, bh);
        }
    }
    // GEMM2: C2 = H @ W3 (K=32)
#pragma unroll
    for (int s = 0; s < 2; s++) {
        uint4 ah = ((const uint4*)hFH)[(warp*2 + s)*32 + lane];
        uint4 al = ((const uint4*)hFL)[(warp*2 + s)*32 + lane];
#pragma unroll
        for (int nt = 0; nt < 8; nt++) {
            uint2 bh = ((const uint2*)b2FH)[(nt*2 + s)*32 + lane];
            uint2 bl = ((const uint2*)b2FL)[(nt*2 + s)*32 + lane];
            MMA16816(c2[nt], ah, bh);
            MMA16816(c2[nt], ah, bl);
            MMA16816(c2[nt], al, bh);
        }
    }

    // ================= combine: out[n,o] = sum_rows C1 * (C2 + b3) =================
    {
        const int tig = lane & 3;
#pragma unroll
        for (int nt = 0; nt < 8; nt++) {
            float b3e = sb3[8*nt + 2*tig];
            float b3o = sb3[8*nt + 2*tig + 1];
            float s0 = c1[nt][0]*(c2[nt][0] + b3e) + c1[nt][2]*(c2[nt][2] + b3e);
            float s1 = c1[nt][1]*(c2[nt][1] + b3o) + c1[nt][3]*(c2[nt][3] + b3o);
#pragma unroll
            for (int msk = 4; msk <= 16; msk <<= 1) {
                s0 += __shfl_xor_sync(0xffffffffu, s0, msk);
                s1 += __shfl_xor_sync(0xffffffffu, s1, msk);
            }
            if (lane < 4) {
                sOut[warp*NO + 8*nt + 2*tig]     = s0;
                sOut[warp*NO + 8*nt + 2*tig + 1] = s1;
            }
        }
    }

    __syncthreads();

    // ================= epilogue: out (B, O, N) + bias =================
    if (tid < 128) {
        int o = tid >> 1, half = tid & 1;
        float4 rr;
        rr.x = sOut[(half*4+0)*NO + o] + sBias[o];
        rr.y = sOut[(half*4+1)*NO + o] + sBias[o];
        rr.z = sOut[(half*4+2)*NO + o] + sBias[o];
        rr.w = sOut[(half*4+3)*NO + o] + sBias[o];
        *(float4*)(out + ((size_t)b*NO + o)*NN + n0 + half*4) = rr;
    }

    // ---- support_points passthrough ----
    if (copy_sp) {
        for (int idx = blk*NTHREADS + tid; idx < SPN; idx += gridDim.x*NTHREADS)
            out[BON + idx] = support[idx];
    }
}

extern "C" void kernel_launch(void* const* d_in, const int* in_sizes, int n_in,
                              void* d_out, int out_size) {
    const float* input   = (const float*)d_in[0];
    const float* points  = (const float*)d_in[1];
    const float* support = (const float*)d_in[2];
    const float* weight  = (const float*)d_in[3];
    const float* bias    = (const float*)d_in[4];
    const float* W1      = (const float*)d_in[5];
    const float* b1      = (const float*)d_in[6];
    const float* W2      = (const float*)d_in[7];
    const float* b2      = (const float*)d_in[8];
    const float* W3      = (const float*)d_in[9];
    const float* b3      = (const float*)d_in[10];

    static int inited = 0;
    if (!inited) {
        cudaFuncSetAttribute(pccn_kernel,
                             cudaFuncAttributeMaxDynamicSharedMemorySize,
                             SMEM_BYTES);
        inited = 1;
    }
    int copy_sp = (out_size > BON) ? 1 : 0;
    pccn_kernel<<<NB*(NN/TN), NTHREADS, SMEM_BYTES>>>(
        input, points, support, weight, bias, W1, b1, W2, b2, W3, b3,
        (float*)d_out, copy_sp);
}

// round 11
// speedup vs baseline: 2.3073x; 1.3148x over previous
#include <cuda_runtime.h>
#include <cuda_bf16.h>

#define NB 8
#define NI 64
#define NO 64
#define NN 8192
#define NK 16
#define ND 3
#define NH1 16
#define NH2 32
#define TN 8
#define ROWS 128
#define NTHREADS 256
#define BON (NB*NO*NN)
#define SPN (NB*ND*NN)
#define CSTRIDE (NN*NK)      // 131072: element stride between i-channels of input

typedef unsigned long long u64;
typedef unsigned int u32;

// ---- smem byte offsets ----
#define SM_BFH   0            // GEMM1 B hi frags: 32 blocks x 32 lanes x uint2 = 8192 B
#define SM_BFL   8192
#define SM_B2FH  16384        // GEMM2 B hi frags: 16 blocks x 32 x uint2 = 4096 B
#define SM_B2FL  20480
#define SM_SCR   24576        // H scratch fp32 [row:128][42 words padded] = 21504 B
#define SM_SMALL 46080
#define SMEM_BYTES (SM_SMALL + 1248*4)
#define SCR_PAD 42

__device__ __forceinline__ u64 pack2(float x, float y) {
    u64 r; asm("mov.b64 %0,{%1,%2};" : "=l"(r) : "f"(x), "f"(y)); return r;
}
__device__ __forceinline__ u64 fma2(u64 a, u64 b, u64 c) {
    u64 d; asm("fma.rn.f32x2 %0,%1,%2,%3;" : "=l"(d) : "l"(a), "l"(b), "l"(c)); return d;
}
__device__ __forceinline__ float2 unpack2(u64 v) {
    float2 f; asm("mov.b64 {%0,%1},%2;" : "=f"(f.x), "=f"(f.y) : "l"(v)); return f;
}
__device__ __forceinline__ u32 bf2bits(__nv_bfloat162 h) { return *reinterpret_cast<u32*>(&h); }

__device__ __forceinline__ void split_pair(float f0, float f1, u32& hi, u32& lo) {
    __nv_bfloat162 hb = __float22bfloat162_rn(make_float2(f0, f1));
    float2 hf = __bfloat1622float2(hb);
    __nv_bfloat162 lb = __float22bfloat162_rn(make_float2(f0 - hf.x, f1 - hf.y));
    hi = bf2bits(hb); lo = bf2bits(lb);
}

#define MMA16816(c, a, b) \
    asm volatile("mma.sync.aligned.m16n8k16.row.col.f32.bf16.bf16.f32 " \
        "{%0,%1,%2,%3}, {%4,%5,%6,%7}, {%8,%9}, {%0,%1,%2,%3};" \
        : "+f"((c)[0]), "+f"((c)[1]), "+f"((c)[2]), "+f"((c)[3]) \
        : "r"((a).x), "r"((a).y), "r"((a).z), "r"((a).w), \
          "r"((b).x), "r"((b).y))

__global__ void __launch_bounds__(NTHREADS, 2)
pccn_kernel(const float* __restrict__ input, const float* __restrict__ points,
            const float* __restrict__ support, const float* __restrict__ weight,
            const float* __restrict__ bias, const float* __restrict__ W1,
            const float* __restrict__ b1, const float* __restrict__ W2,
            const float* __restrict__ b2, const float* __restrict__ W3,
            const float* __restrict__ b3, float* __restrict__ out, int copy_sp)
{
    extern __shared__ char smemc[];
    u32* bFH  = (u32*)(smemc + SM_BFH);
    u32* bFL  = (u32*)(smemc + SM_BFL);
    u32* b2FH = (u32*)(smemc + SM_B2FH);
    u32* b2FL = (u32*)(smemc + SM_B2FL);
    float* scr = (float*)(smemc + SM_SCR);
    float* sW1   = (float*)(smemc + SM_SMALL);
    float* sb1   = sW1 + 48;
    float* sW2   = sb1 + 16;
    float* sb2   = sW2 + 512;
    float* sb3   = sb2 + 32;
    float* sBias = sb3 + 64;
    float* sOut  = sBias + 64;        // [n_local:8][o:64]

    const int tid  = threadIdx.x;
    const int warp = tid >> 5;
    const int lane = tid & 31;
    const int gid  = lane >> 2;
    const int tig  = lane & 3;
    const int blk  = blockIdx.x;
    const int b    = blk >> 10;
    const int n0   = (blk & 1023) * TN;

    // ========== B staging: warp q owns nt=q; conflict-free STS.64 ==========
    {
        const int n = 8*warp + gid;
#pragma unroll
        for (int s = 0; s < 4; s++) {
            int k0 = 16*s + 2*tig;
            float w00 = weight[k0*NO + n],     w01 = weight[(k0+1)*NO + n];
            float w10 = weight[(k0+8)*NO + n], w11 = weight[(k0+9)*NO + n];
            u32 h0,l0,h1,l1;
            split_pair(w00, w01, h0, l0);
            split_pair(w10, w11, h1, l1);
            ((uint2*)bFH)[(warp*4 + s)*32 + lane] = make_uint2(h0, h1);
            ((uint2*)bFL)[(warp*4 + s)*32 + lane] = make_uint2(l0, l1);
        }
#pragma unroll
        for (int s = 0; s < 2; s++) {
            int k0 = 16*s + 2*tig;
            float w00 = W3[k0*NO + n],     w01 = W3[(k0+1)*NO + n];
            float w10 = W3[(k0+8)*NO + n], w11 = W3[(k0+9)*NO + n];
            u32 h0,l0,h1,l1;
            split_pair(w00, w01, h0, l0);
            split_pair(w10, w11, h1, l1);
            ((uint2*)b2FH)[(warp*2 + s)*32 + lane] = make_uint2(h0, h1);
            ((uint2*)b2FL)[(warp*2 + s)*32 + lane] = make_uint2(l0, l1);
        }
    }
    // ---- small arrays ----
    for (int idx = tid; idx < NH1*NH2; idx += NTHREADS) sW2[idx] = W2[idx];
    if (tid < 48) sW1[tid]  = W1[tid];
    if (tid < 16) sb1[tid]  = b1[tid];
    if (tid < 32) sb2[tid]  = b2[tid];
    if (tid < 64) sb3[tid]  = b3[tid];
    if (tid < 64) sBias[tid] = bias[tid];

    __syncthreads();

    // ========== X direct loads: warp w reads its own 16 rows (8 floats/lane/s) ==========
    float xr[32];
    {
        const float* base = input + (size_t)b*NI*CSTRIDE + (size_t)n0*NK;
        const int r0 = 16*warp + gid;
#pragma unroll
        for (int s = 0; s < 4; s++) {
            const float* pc = base + (size_t)(16*s + 2*tig)*CSTRIDE;
            xr[s*8+0] = pc[r0];
            xr[s*8+1] = pc[CSTRIDE + r0];
            xr[s*8+2] = pc[r0 + 8];
            xr[s*8+3] = pc[CSTRIDE + r0 + 8];
            xr[s*8+4] = pc[8*CSTRIDE + r0];
            xr[s*8+5] = pc[9*CSTRIDE + r0];
            xr[s*8+6] = pc[8*CSTRIDE + r0 + 8];
            xr[s*8+7] = pc[9*CSTRIDE + r0 + 8];
        }
    }

    // ========== coords + MLP -> fp32 scratch (threads 0..127, row = tid) ==========
    if (tid < ROWS) {
        const int row = tid;
        const int k = row & 15;
        const int n = n0 + (row >> 4);
        float p0 = points[(((size_t)b*ND + 0)*NN + n)*NK + k] - support[((size_t)b*ND + 0)*NN + n];
        float p1 = points[(((size_t)b*ND + 1)*NN + n)*NK + k] - support[((size_t)b*ND + 1)*NN + n];
        float p2 = points[(((size_t)b*ND + 2)*NN + n)*NK + k] - support[((size_t)b*ND + 2)*NN + n];
        float sq = p0*p0 + p1*p1 + p2*p2;
        float m = sq;
#pragma unroll
        for (int off = 8; off > 0; off >>= 1)
            m = fmaxf(m, __shfl_xor_sync(0xffffffffu, m, off));
        float maxi = sqrtf(m);
        maxi += (maxi == 0.0f) ? 1.0f : 0.0f;
        float inv = 1.0f / maxi;
        float x0 = p0*inv, x1 = p1*inv, x2 = p2*inv;

        float h1[NH1];
#pragma unroll
        for (int a = 0; a < NH1; a++) {
            float v = sb1[a] + x0*sW1[a] + x1*sW1[16 + a] + x2*sW1[32 + a];
            h1[a] = fmaxf(v, 0.0f);
        }
        u64 h2p[NH2/2];
#pragma unroll
        for (int jp = 0; jp < NH2/2; jp++) h2p[jp] = ((const u64*)sb2)[jp];
#pragma unroll
        for (int a = 0; a < NH1; a++) {
            u64 xd = pack2(h1[a], h1[a]);
            const u64* wrow = (const u64*)(sW2 + a*NH2);
#pragma unroll
            for (int jp = 0; jp < NH2/2; jp++) h2p[jp] = fma2(xd, wrow[jp], h2p[jp]);
        }
#pragma unroll
        for (int jp = 0; jp < 16; jp++) {
            float2 v = unpack2(h2p[jp]);
            v.x = fmaxf(v.x, 0.0f); v.y = fmaxf(v.y, 0.0f);
            *(float2*)(scr + row*SCR_PAD + 2*jp) = v;
        }
    }

    __syncthreads();

    // ========== GEMMs via mma.sync (warp w -> rows 16w..16w+15 = n_local w) ==========
    float c1[8][4], c2[8][4];
#pragma unroll
    for (int nt = 0; nt < 8; nt++)
#pragma unroll
        for (int r = 0; r < 4; r++) { c1[nt][r] = 0.0f; c2[nt][r] = 0.0f; }

    // GEMM1: C1 = X @ W (K=64), A from registers (split inline)
#pragma unroll
    for (int s = 0; s < 4; s++) {
        uint4 ah, al;
        split_pair(xr[s*8+0], xr[s*8+1], ah.x, al.x);
        split_pair(xr[s*8+2], xr[s*8+3], ah.y, al.y);
        split_pair(xr[s*8+4], xr[s*8+5], ah.z, al.z);
        split_pair(xr[s*8+6], xr[s*8+7], ah.w, al.w);
#pragma unroll
        for (int nt = 0; nt < 8; nt++) {
            uint2 bh = ((const uint2*)bFH)[(nt*4 + s)*32 + lane];
            uint2 bl = ((const uint2*)bFL)[(nt*4 + s)*32 + lane];
            MMA16816(c1[nt], ah, bh);
            MMA16816(c1[nt], ah, bl);
            MMA16816(c1[nt], al, bh);
        }
    }
    // GEMM2: C2 = H @ W3 (K=32), A from scratch (split inline)
#pragma unroll
    for (int s = 0; s < 2; s++) {
        const int c0 = 16*s + 2*tig;
        const int r0 = 16*warp + gid;
        float2 p00 = *(const float2*)(scr + r0*SCR_PAD + c0);
        float2 p10 = *(const float2*)(scr + (r0+8)*SCR_PAD + c0);
        float2 p01 = *(const float2*)(scr + r0*SCR_PAD + c0 + 8);
        float2 p11 = *(const float2*)(scr + (r0+8)*SCR_PAD + c0 + 8);
        uint4 ah, al;
        split_pair(p00.x, p00.y, ah.x, al.x);
        split_pair(p10.x, p10.y, ah.y, al.y);
        split_pair(p01.x, p01.y, ah.z, al.z);
        split_pair(p11.x, p11.y, ah.w, al.w);
#pragma unroll
        for (int nt = 0; nt < 8; nt++) {
            uint2 bh = ((const uint2*)b2FH)[(nt*2 + s)*32 + lane];
            uint2 bl = ((const uint2*)b2FL)[(nt*2 + s)*32 + lane];
            MMA16816(c2[nt], ah, bh);
            MMA16816(c2[nt], ah, bl);
            MMA16816(c2[nt], al, bh);
        }
    }

    // ========== combine: out[n,o] = sum_rows C1 * (C2 + b3) ==========
    {
#pragma unroll
        for (int nt = 0; nt < 8; nt++) {
            float b3e = sb3[8*nt + 2*tig];
            float b3o = sb3[8*nt + 2*tig + 1];
            float s0 = c1[nt][0]*(c2[nt][0] + b3e) + c1[nt][2]*(c2[nt][2] + b3e);
            float s1 = c1[nt][1]*(c2[nt][1] + b3o) + c1[nt][3]*(c2[nt][3] + b3o);
#pragma unroll
            for (int msk = 4; msk <= 16; msk <<= 1) {
                s0 += __shfl_xor_sync(0xffffffffu, s0, msk);
                s1 += __shfl_xor_sync(0xffffffffu, s1, msk);
            }
            if (lane < 4) {
                sOut[warp*NO + 8*nt + 2*tig]     = s0;
                sOut[warp*NO + 8*nt + 2*tig + 1] = s1;
            }
        }
    }

    __syncthreads();

    // ========== epilogue: out (B, O, N) + bias ==========
    if (tid < 128) {
        int o = tid >> 1, half = tid & 1;
        float4 rr;
        rr.x = sOut[(half*4+0)*NO + o] + sBias[o];
        rr.y = sOut[(half*4+1)*NO + o] + sBias[o];
        rr.z = sOut[(half*4+2)*NO + o] + sBias[o];
        rr.w = sOut[(half*4+3)*NO + o] + sBias[o];
        *(float4*)(out + ((size_t)b*NO + o)*NN + n0 + half*4) = rr;
    }

    // ---- support_points passthrough ----
    if (copy_sp) {
        for (int idx = blk*NTHREADS + tid; idx < SPN; idx += gridDim.x*NTHREADS)
            out[BON + idx] = support[idx];
    }
}

extern "C" void kernel_launch(void* const* d_in, const int* in_sizes, int n_in,
                              void* d_out, int out_size) {
    const float* input   = (const float*)d_in[0];
    const float* points  = (const float*)d_in[1];
    const float* support = (const float*)d_in[2];
    const float* weight  = (const float*)d_in[3];
    const float* bias    = (const float*)d_in[4];
    const float* W1      = (const float*)d_in[5];
    const float* b1      = (const float*)d_in[6];
    const float* W2      = (const float*)d_in[7];
    const float* b2      = (const float*)d_in[8];
    const float* W3      = (const float*)d_in[9];
    const float* b3      = (const float*)d_in[10];

    static int inited = 0;
    if (!inited) {
        cudaFuncSetAttribute(pccn_kernel,
                             cudaFuncAttributeMaxDynamicSharedMemorySize,
                             SMEM_BYTES);
        inited = 1;
    }
    int copy_sp = (out_size > BON) ? 1 : 0;
    pccn_kernel<<<NB*(NN/TN), NTHREADS, SMEM_BYTES>>>(
        input, points, support, weight, bias, W1, b1, W2, b2, W3, b3,
        (float*)d_out, copy_sp);
}